// round 13
// baseline (speedup 1.0000x reference)
#include <cuda_runtime.h>
#include <cuda_bf16.h>
#include <cstdint>

// y[b] = a_0 + sum_n bk[n] * tanh( dot(ck[n,:], z[b,:]) + dk[n] )
// B = 2097152 (multiple of 16), Z = 16, N = 64.
//
// HMMA m16n8k16 bf16, bf16x3 split, fp32 accum, dk in C init. Occ-3 config
// (R10) + this round: pointer-strided addressing (no per-iter index math),
// no dead clamps/guards (B % 16 == 0), j-pair interleaving for MMA/MUFU
// latency overlap, merged dk/bk broadcast LDS.128.

#define ZD    16
#define NN    64
#define TPB   256
#define WPB   8
#define GRIDB 444      // 148 SMs * 3 CTAs: one persistent wave
#define CHUNK 16       // batch rows per warp-iteration

static __device__ __forceinline__ float tanh_fast(float x) {
    float y; asm("tanh.approx.f32 %0, %1;" : "=f"(y) : "f"(x)); return y;
}
static __device__ __forceinline__ uint32_t pack_bf16x2(float lo, float hi) {
    uint32_t r; asm("cvt.rn.bf16x2.f32 %0, %1, %2;" : "=r"(r) : "f"(hi), "f"(lo)); return r;
}
static __device__ __forceinline__ float bf_lo_f(uint32_t h) { return __uint_as_float(h << 16); }
static __device__ __forceinline__ float bf_hi_f(uint32_t h) { return __uint_as_float(h & 0xFFFF0000u); }

static __device__ __forceinline__ void split2(float x, float y, uint32_t& h, uint32_t& l) {
    h = pack_bf16x2(x, y);
    l = pack_bf16x2(x - bf_lo_f(h), y - bf_hi_f(h));
}

static __device__ __forceinline__ void mma_bf16(
    float& d0, float& d1, float& d2, float& d3,
    uint32_t a0, uint32_t a1, uint32_t a2, uint32_t a3,
    uint32_t b0, uint32_t b1)
{
    asm volatile(
        "mma.sync.aligned.m16n8k16.row.col.f32.bf16.bf16.f32 "
        "{%0,%1,%2,%3}, {%4,%5,%6,%7}, {%8,%9}, {%0,%1,%2,%3};"
        : "+f"(d0), "+f"(d1), "+f"(d2), "+f"(d3)
        : "r"(a0), "r"(a1), "r"(a2), "r"(a3), "r"(b0), "r"(b1));
}

__global__ __launch_bounds__(TPB, 3)
void mave_hmma_kernel(const float2* __restrict__ zp,
                      const float* __restrict__ a0p,
                      const float* __restrict__ bkp,
                      const float* __restrict__ ckp,
                      const float* __restrict__ dkp,
                      float*       __restrict__ out,
                      int nchunks)
{
    __shared__ uint4  sfrag[8][32];  // [j][lane] = (bh0, bh1, bl0, bl1), 4 KB
    __shared__ float4 sdb[8][4];     // [j][tg] = (dk0, dk1, bk0, bk1), 512 B

    const int tid  = threadIdx.x;
    const int wid  = tid >> 5;
    const int lane = tid & 31;
    const int g    = lane >> 2;   // groupID: row within 8-row half / B-col
    const int tg   = lane & 3;    // thread-in-group: k-pair / D-col pair

    // warp w builds the B fragment for j = w (identical across blocks)
    {
        const int j = wid;
        const float2* cp = reinterpret_cast<const float2*>(ckp + (8 * j + g) * ZD);
        float2 x0 = cp[tg];
        float2 x1 = cp[tg + 4];
        uint32_t h0, l0, h1, l1;
        split2(x0.x, x0.y, h0, l0);
        split2(x1.x, x1.y, h1, l1);
        sfrag[j][lane] = make_uint4(h0, h1, l0, l1);
    }
    if (tid < 32) {
        int j = tid >> 2, t = tid & 3;
        sdb[j][t] = make_float4(dkp[8 * j + 2 * t], dkp[8 * j + 2 * t + 1],
                                bkp[8 * j + 2 * t], bkp[8 * j + 2 * t + 1]);
    }
    __syncthreads();

    const float a0v = a0p[0];
    const int W = GRIDB * WPB;          // total warps

    int c = blockIdx.x * WPB + wid;
    if (c >= nchunks) return;

    // ---- strided pointers: all addresses advance by constants ----
    // z: row r0 = c*16+g -> float2 index c*128 + g*8 + tg.
    //    x00=p[0], x01=p[4], x10=p[64], x11=p[68]; stride W*128 float2.
    const float2* p = zp + (size_t)c * (CHUNK * 8) + g * 8 + tg;
    float*        q = out + (size_t)c * CHUNK + g;   // store q[0], q[8]; stride W*16

    // ---- prime the pipeline ----
    float2 x00 = p[0], x10 = p[64], x01 = p[4], x11 = p[68];

    while (true) {
        // ---- consume buffer: bf16 hi/lo split into A fragments ----
        uint32_t ah0, al0, ah1, al1, ah2, al2, ah3, al3;
        split2(x00.x, x00.y, ah0, al0);
        split2(x10.x, x10.y, ah1, al1);
        split2(x01.x, x01.y, ah2, al2);
        split2(x11.x, x11.y, ah3, al3);

        const int cn = c + W;
        const bool more = (cn < nchunks);

        // ---- prefetch next chunk (overlaps compute below) ----
        if (more) {
            p += W * (CHUNK * 8);
            x00 = p[0]; x10 = p[64]; x01 = p[4]; x11 = p[68];
        }

        float accL = 0.0f, accH = 0.0f;

        // ---- j-pairs: two independent MMA->tanh chains in flight ----
        #pragma unroll
        for (int jj = 0; jj < 8; jj += 2) {
            const uint4  fa  = sfrag[jj][lane];
            const uint4  fb  = sfrag[jj + 1][lane];
            const float4 dba = sdb[jj][tg];
            const float4 dbb = sdb[jj + 1][tg];

            float a0_ = dba.x, a1_ = dba.y, a2_ = dba.x, a3_ = dba.y;
            float b0_ = dbb.x, b1_ = dbb.y, b2_ = dbb.x, b3_ = dbb.y;

            mma_bf16(a0_, a1_, a2_, a3_, ah0, ah1, ah2, ah3, fa.x, fa.y);
            mma_bf16(b0_, b1_, b2_, b3_, ah0, ah1, ah2, ah3, fb.x, fb.y);
            mma_bf16(a0_, a1_, a2_, a3_, al0, al1, al2, al3, fa.x, fa.y);
            mma_bf16(b0_, b1_, b2_, b3_, al0, al1, al2, al3, fb.x, fb.y);
            mma_bf16(a0_, a1_, a2_, a3_, ah0, ah1, ah2, ah3, fa.z, fa.w);
            mma_bf16(b0_, b1_, b2_, b3_, ah0, ah1, ah2, ah3, fb.z, fb.w);

            accL = fmaf(dba.z, tanh_fast(a0_), accL);
            accL = fmaf(dba.w, tanh_fast(a1_), accL);
            accH = fmaf(dba.z, tanh_fast(a2_), accH);
            accH = fmaf(dba.w, tanh_fast(a3_), accH);
            accL = fmaf(dbb.z, tanh_fast(b0_), accL);
            accL = fmaf(dbb.w, tanh_fast(b1_), accL);
            accH = fmaf(dbb.z, tanh_fast(b2_), accH);
            accH = fmaf(dbb.w, tanh_fast(b3_), accH);
        }

        // ---- reduce over the 4 column-threads of each row ----
        accL += __shfl_xor_sync(0xFFFFFFFFu, accL, 1);
        accL += __shfl_xor_sync(0xFFFFFFFFu, accL, 2);
        accH += __shfl_xor_sync(0xFFFFFFFFu, accH, 1);
        accH += __shfl_xor_sync(0xFFFFFFFFu, accH, 2);

        if (tg == 0) {
            q[0] = a0v + accL;
            q[8] = a0v + accH;
        }

        if (!more) break;
        q += W * CHUNK;
        c = cn;
    }
}

extern "C" void kernel_launch(void* const* d_in, const int* in_sizes, int n_in,
                              void* d_out, int out_size) {
    const float* z  = (const float*)d_in[0];
    const float* a0 = (const float*)d_in[1];
    const float* bk = (const float*)d_in[2];
    const float* ck = (const float*)d_in[3];
    const float* dk = (const float*)d_in[4];
    float* out = (float*)d_out;

    const int B = in_sizes[0] / ZD;       // 2097152, multiple of CHUNK
    const int nchunks = B / CHUNK;

    mave_hmma_kernel<<<GRIDB, TPB>>>((const float2*)z, a0, bk, ck, dk, out, nchunks);
}

// round 15
// speedup vs baseline: 1.0511x; 1.0511x over previous
#include <cuda_runtime.h>
#include <cuda_bf16.h>
#include <cstdint>

// y[b] = a_0 + sum_n bk[n] * tanh( dot(ck[n,:], z[b,:]) + dk[n] )
// B = 2097152 (multiple of 16), Z = 16, N = 64.
//
// R10 structure (occ 3, smem B-fragments, prefetch pipeline) + two trims:
// merged dk/bk broadcast LDS.128, and dead clamp/guard removal (B % 16 == 0).

#define ZD    16
#define NN    64
#define TPB   256
#define WPB   8
#define GRIDB 444      // 148 SMs * 3 CTAs: one persistent wave
#define CHUNK 16       // batch rows per warp-iteration

static __device__ __forceinline__ float tanh_fast(float x) {
    float y; asm("tanh.approx.f32 %0, %1;" : "=f"(y) : "f"(x)); return y;
}
static __device__ __forceinline__ uint32_t pack_bf16x2(float lo, float hi) {
    uint32_t r; asm("cvt.rn.bf16x2.f32 %0, %1, %2;" : "=r"(r) : "f"(hi), "f"(lo)); return r;
}
static __device__ __forceinline__ float bf_lo_f(uint32_t h) { return __uint_as_float(h << 16); }
static __device__ __forceinline__ float bf_hi_f(uint32_t h) { return __uint_as_float(h & 0xFFFF0000u); }

static __device__ __forceinline__ void split2(float x, float y, uint32_t& h, uint32_t& l) {
    h = pack_bf16x2(x, y);
    l = pack_bf16x2(x - bf_lo_f(h), y - bf_hi_f(h));
}

static __device__ __forceinline__ void mma_bf16(
    float& d0, float& d1, float& d2, float& d3,
    uint32_t a0, uint32_t a1, uint32_t a2, uint32_t a3,
    uint32_t b0, uint32_t b1)
{
    asm volatile(
        "mma.sync.aligned.m16n8k16.row.col.f32.bf16.bf16.f32 "
        "{%0,%1,%2,%3}, {%4,%5,%6,%7}, {%8,%9}, {%0,%1,%2,%3};"
        : "+f"(d0), "+f"(d1), "+f"(d2), "+f"(d3)
        : "r"(a0), "r"(a1), "r"(a2), "r"(a3), "r"(b0), "r"(b1));
}

__global__ __launch_bounds__(TPB, 3)
void mave_hmma_kernel(const float2* __restrict__ zp,
                      const float* __restrict__ a0p,
                      const float* __restrict__ bkp,
                      const float* __restrict__ ckp,
                      const float* __restrict__ dkp,
                      float*       __restrict__ out,
                      int nchunks)
{
    __shared__ uint4  sfrag[8][32];  // [j][lane] = (bh0, bh1, bl0, bl1), 4 KB
    __shared__ float4 sdb[8][4];     // [j][tg] = (dk0, dk1, bk0, bk1), 512 B

    const int tid  = threadIdx.x;
    const int wid  = tid >> 5;
    const int lane = tid & 31;
    const int g    = lane >> 2;   // groupID: row within 8-row half / B-col
    const int tg   = lane & 3;    // thread-in-group: k-pair / D-col pair

    // warp w builds the B fragment for j = w (identical across blocks)
    {
        const int j = wid;
        const float2* cp = reinterpret_cast<const float2*>(ckp + (8 * j + g) * ZD);
        float2 x0 = cp[tg];
        float2 x1 = cp[tg + 4];
        uint32_t h0, l0, h1, l1;
        split2(x0.x, x0.y, h0, l0);
        split2(x1.x, x1.y, h1, l1);
        sfrag[j][lane] = make_uint4(h0, h1, l0, l1);
    }
    if (tid < 32) {
        int j = tid >> 2, t = tid & 3;
        sdb[j][t] = make_float4(dkp[8 * j + 2 * t], dkp[8 * j + 2 * t + 1],
                                bkp[8 * j + 2 * t], bkp[8 * j + 2 * t + 1]);
    }
    __syncthreads();

    const float a0v = a0p[0];
    const int warp0  = blockIdx.x * WPB + wid;
    const int nwarps = GRIDB * WPB;

    int c = warp0;
    if (c >= nchunks) return;

    // ---- prime the pipeline: load chunk c's z rows (raw float2s) ----
    float2 x00, x10, x01, x11;
    {
        int base = c * CHUNK;
        int r0 = base + g;
        int r1 = base + g + 8;
        x00 = zp[r0 * 8 + tg];
        x10 = zp[r1 * 8 + tg];
        x01 = zp[r0 * 8 + tg + 4];
        x11 = zp[r1 * 8 + tg + 4];
    }

    while (c < nchunks) {
        // ---- consume the buffer: bf16 hi/lo split into A fragments ----
        uint32_t ah0, al0, ah1, al1, ah2, al2, ah3, al3;
        split2(x00.x, x00.y, ah0, al0);
        split2(x10.x, x10.y, ah1, al1);
        split2(x01.x, x01.y, ah2, al2);
        split2(x11.x, x11.y, ah3, al3);

        const int base = c * CHUNK;
        const int cn = c + nwarps;

        // ---- prefetch next chunk's z; overlaps the MMAs + epilogue below ----
        if (cn < nchunks) {
            int nb = cn * CHUNK;
            int r0 = nb + g;
            int r1 = nb + g + 8;
            x00 = zp[r0 * 8 + tg];
            x10 = zp[r1 * 8 + tg];
            x01 = zp[r0 * 8 + tg + 4];
            x11 = zp[r1 * 8 + tg + 4];
        }

        float acc_lo = 0.0f, acc_hi = 0.0f;

        #pragma unroll
        for (int j = 0; j < 8; j++) {
            uint4  f  = sfrag[j][lane];   // one LDS.128: bh0, bh1, bl0, bl1
            float4 db = sdb[j][tg];       // one broadcast LDS.128: dk0,dk1,bk0,bk1

            float d0 = db.x, d1 = db.y, d2 = db.x, d3 = db.y;

            mma_bf16(d0, d1, d2, d3, ah0, ah1, ah2, ah3, f.x, f.y);
            mma_bf16(d0, d1, d2, d3, al0, al1, al2, al3, f.x, f.y);
            mma_bf16(d0, d1, d2, d3, ah0, ah1, ah2, ah3, f.z, f.w);

            acc_lo = fmaf(db.z, tanh_fast(d0), acc_lo);
            acc_lo = fmaf(db.w, tanh_fast(d1), acc_lo);
            acc_hi = fmaf(db.z, tanh_fast(d2), acc_hi);
            acc_hi = fmaf(db.w, tanh_fast(d3), acc_hi);
        }

        // ---- reduce over the 4 column-threads of each row ----
        acc_lo += __shfl_xor_sync(0xFFFFFFFFu, acc_lo, 1);
        acc_lo += __shfl_xor_sync(0xFFFFFFFFu, acc_lo, 2);
        acc_hi += __shfl_xor_sync(0xFFFFFFFFu, acc_hi, 1);
        acc_hi += __shfl_xor_sync(0xFFFFFFFFu, acc_hi, 2);

        if (tg == 0) {
            out[base + g]     = a0v + acc_lo;
            out[base + g + 8] = a0v + acc_hi;
        }
        c = cn;
    }
}

extern "C" void kernel_launch(void* const* d_in, const int* in_sizes, int n_in,
                              void* d_out, int out_size) {
    const float* z  = (const float*)d_in[0];
    const float* a0 = (const float*)d_in[1];
    const float* bk = (const float*)d_in[2];
    const float* ck = (const float*)d_in[3];
    const float* dk = (const float*)d_in[4];
    float* out = (float*)d_out;

    const int B = in_sizes[0] / ZD;       // 2097152, multiple of CHUNK
    const int nchunks = B / CHUNK;

    mave_hmma_kernel<<<GRIDB, TPB>>>((const float2*)z, a0, bk, ck, dk, out, nchunks);
}